// round 14
// baseline (speedup 1.0000x reference)
#include <cuda_runtime.h>
#include <cuda_bf16.h>

#define N_TRIALS   8
#define T_TOTAL    600
#define N_NEURONS  30000
#define T_USE      500
#define N_SAMPLES  50
#define MAX_COUNT  200
#define N_BINS     16
#define EPS        1e-7f
#define SYNC_COST  10.0f

#define NJ          8                 // per-sample id chunks (dynamic split of [0,cnt))
#define JMAX        32                // >= ceil(MAX_COUNT/NJ) = 25

__constant__ int c_bins[N_BINS] = {1,1,2,3,4,6,9,13,18,26,38,55,78,113,162,234};

// Scratch (device globals: allocation is forbidden)
__device__ float        g_part[NJ * N_SAMPLES * T_USE];  // partial gather sums
__device__ float        g_fano[N_BINS * N_SAMPLES];      // per-(bin,sample) fano
__device__ unsigned int g_ticket;                        // last-block ticket (self-resets)

// ---------------------------------------------------------------------------
// Phase 1: gather partial sums (R4/R13 topology -- measured at the DRAM
// unique-line floor; UNCHANGED).
// Block = (sample, t-chunk, j-chunk); thread owns one t; 8-wide unrolled
// scattered LDGs. mask is prefix-form (arange < count) => effective count =
// sum(mask); ids[0:cnt] are exactly the active ids (duplicates preserved).
// j-chunks split the ACTIVE range [0,cnt) evenly.
// sample_ids arrives as int32 (JAX x64-disabled demotes int64 -> int32).
// ---------------------------------------------------------------------------
__global__ void __launch_bounds__(128)
gather_kernel(const float* __restrict__ spikes,
              const int*   __restrict__ trials,
              const int*   __restrict__ ids,
              const float* __restrict__ mask)
{
    __shared__ int s_ids[JMAX];
    __shared__ int s_cnt;

    const int s   = blockIdx.x;
    const int jc  = blockIdx.z;
    const int tid = threadIdx.x;

    if (tid == 0) s_cnt = 0;
    __syncthreads();

    int local = 0;
    for (int j = tid; j < MAX_COUNT; j += 128)
        if (mask[s * MAX_COUNT + j] != 0.0f) local++;
    if (local) atomicAdd(&s_cnt, local);
    __syncthreads();

    const int cnt = s_cnt;
    const int lo  = (jc * cnt) / NJ;
    const int m   = ((jc + 1) * cnt) / NJ - lo;   // <= 25
    if (tid < m)
        s_ids[tid] = ids[s * MAX_COUNT + lo + tid];
    __syncthreads();

    const int t = blockIdx.y * 128 + tid;
    if (t >= T_USE) return;

    float acc = 0.0f;
    if (m > 0) {
        const float* __restrict__ base =
            spikes + (size_t)trials[s] * ((size_t)T_TOTAL * N_NEURONS)
                   + (size_t)t * N_NEURONS;
        int j = 0;
        for (; j + 8 <= m; j += 8) {
            float v0 = __ldg(base + s_ids[j + 0]);
            float v1 = __ldg(base + s_ids[j + 1]);
            float v2 = __ldg(base + s_ids[j + 2]);
            float v3 = __ldg(base + s_ids[j + 3]);
            float v4 = __ldg(base + s_ids[j + 4]);
            float v5 = __ldg(base + s_ids[j + 5]);
            float v6 = __ldg(base + s_ids[j + 6]);
            float v7 = __ldg(base + s_ids[j + 7]);
            acc += ((v0 + v1) + (v2 + v3)) + ((v4 + v5) + (v6 + v7));
        }
        for (; j < m; ++j) acc += __ldg(base + s_ids[j]);
    }
    g_part[(jc * N_SAMPLES + s) * T_USE + t] = acc;
}

// ---------------------------------------------------------------------------
// Phase 2: one block per SAMPLE, 512 threads = 16 warps = one bin per warp.
//   - combine this sample's NJ partials ONCE, vectorized: 125 threads each
//     sum 8 independent float4 (LDG.128) and store one float4 to the smem
//     row (row offsets are 2000B -> 16B aligned). One L2 latency round.
//   - warp w computes bin w from smem (single-pass sum / sum-of-squares,
//     identical per-bin reduction order as before).
//   - last block (ticket, counts to 50) computes per-bin means, MSE, scales,
//     writes out, and resets the ticket for the next graph replay.
// ---------------------------------------------------------------------------
__global__ void __launch_bounds__(512)
fano_kernel(const float* __restrict__ exp_fanos, float* __restrict__ out)
{
    __shared__ float s_row[T_USE];
    __shared__ bool  s_last;

    const int s    = blockIdx.x;               // sample
    const int tid  = threadIdx.x;
    const int lane = tid & 31;
    const int wid  = tid >> 5;                 // 0..15 = bin

    // combine partials -> smem row (vectorized, once per sample)
    if (tid < T_USE / 4) {                     // 125 float4s
        float4 v = make_float4(0.0f, 0.0f, 0.0f, 0.0f);
        #pragma unroll
        for (int c = 0; c < NJ; ++c) {
            const float4 p = __ldg(reinterpret_cast<const float4*>(
                g_part + (size_t)(c * N_SAMPLES + s) * T_USE) + tid);
            v.x += p.x; v.y += p.y; v.z += p.z; v.w += p.w;
        }
        reinterpret_cast<float4*>(s_row)[tid] = v;
    }
    __syncthreads();

    // one bin per warp
    {
        const int bs = c_bins[wid];
        const int nb = T_USE / bs;

        float sum = 0.0f, sumsq = 0.0f;
        for (int k = lane; k < nb; k += 32) {
            const float* rk = s_row + k * bs;
            float c = 0.0f;
            int u = 0;
            for (; u + 4 <= bs; u += 4) {
                float a0 = rk[u], a1 = rk[u+1], a2 = rk[u+2], a3 = rk[u+3];
                c += (a0 + a1) + (a2 + a3);
            }
            for (; u < bs; ++u) c += rk[u];
            sum   += c;
            sumsq += c * c;
        }
        #pragma unroll
        for (int off = 16; off > 0; off >>= 1) {
            sum   += __shfl_down_sync(0xffffffff, sum,   off);
            sumsq += __shfl_down_sync(0xffffffff, sumsq, off);
        }
        if (lane == 0) {
            const float mean = sum / (float)nb;
            const float var  = sumsq / (float)nb - mean * mean;
            g_fano[wid * N_SAMPLES + s] = var / fmaxf(mean, EPS);
        }
    }

    // last-block reduction -> scalar loss
    __threadfence();
    __syncthreads();
    if (tid == 0) {
        unsigned int old = atomicAdd(&g_ticket, 1u);
        s_last = (old == N_SAMPLES - 1);
        if (s_last) g_ticket = 0;              // reset for next graph replay
    }
    __syncthreads();

    if (s_last && wid == 0) {
        float d2 = 0.0f;
        if (lane < N_BINS) {
            float fsum = 0.0f;
            for (int q = 0; q < N_SAMPLES; ++q)
                fsum += g_fano[lane * N_SAMPLES + q];
            const float fm = fsum / (float)N_SAMPLES;
            const float d  = exp_fanos[lane] - fm;
            d2 = d * d;
        }
        #pragma unroll
        for (int off = 16; off > 0; off >>= 1)
            d2 += __shfl_down_sync(0xffffffff, d2, off);
        if (lane == 0)
            out[0] = SYNC_COST * (d2 / (float)N_BINS);
    }
}

// ---------------------------------------------------------------------------
// Inputs (metadata order):
//   0: spikes float32 [8,600,30000]   1: experimental_fanos_mean float32 [16]
//   2: sample_trials int32 [50]       3: sample_ids int32 [50,200]
//   4: sample_mask float32 [50,200]   out: float32 scalar
// ---------------------------------------------------------------------------
extern "C" void kernel_launch(void* const* d_in, const int* in_sizes, int n_in,
                              void* d_out, int out_size)
{
    const float* spikes = (const float*)d_in[0];
    const float* expf_  = (const float*)d_in[1];
    const int*   trials = (const int*)d_in[2];
    const int*   ids    = (const int*)d_in[3];
    const float* mask   = (const float*)d_in[4];
    float*       out    = (float*)d_out;

    dim3 grid(N_SAMPLES, (T_USE + 127) / 128, NJ);
    gather_kernel<<<grid, 128>>>(spikes, trials, ids, mask);
    fano_kernel<<<N_SAMPLES, 512>>>(expf_, out);
}